// round 13
// baseline (speedup 1.0000x reference)
#include <cuda_runtime.h>
#include <math.h>
#include <stdint.h>

#define N_TOK 16384
#define D 512
#define VOCAB 96

// ---------------- device scratch ----------------
__device__ float4 g_U[VOCAB * D];    // (u1r, u1i, u2r, u2i)
__device__ float4 g_V[VOCAB * D];    // (V1r, V1i, V2r, V2i) = U @ W^T
__device__ float4 g_S[VOCAB];        // (S11, S22, S12r, S12i)
__device__ float4 g_phtab[D];        // cosP, sinP, cos2P, sin2P
__device__ float4 g_cols[D];         // bias, gamma, beta, 0
__device__ float4 g_wf[N_TOK];       // wf1r, wf1i, wf2r, wf2i
__device__ float4 g_tokA[VOCAB];     // cos(cpm), sin(cpm), cos(1.3cpm), sin(1.3cpm)
__device__ float2 g_tokB[VOCAB];     // cos(.7cpm), sin(.7cpm)

// ---------------- K0: all trig, fully parallel ----------------
// grid 112 x 256 = 28672 threads:
// [0,12288): U entries (one thread = one d x 4 chars, complex recurrence, fast trig)
//            gid<512 also fills d-tables; 512<=gid<608 per-char trig
// [12288, 28672): per-token wf (precise trig; phases reach ~50 rad)
__global__ __launch_bounds__(256) void setup_kernel(const int* __restrict__ char_idx,
                                                    const int* __restrict__ positions,
                                                    const float* __restrict__ bias,
                                                    const float* __restrict__ gamma,
                                                    const float* __restrict__ beta_ln) {
    const int gid = blockIdx.x * blockDim.x + threadIdx.x;
    const float PI = 3.14159265358979323846f;
    const float TH1 = 2.0f * PI / ((float)VOCAB * (float)D);
    const float TH2 = 4.0f * PI * 1.7f / ((float)VOCAB * (float)D);

    if (gid < 12288) {
        const int d = gid & 511;
        const int c0 = (gid >> 9) * 4;

        float kv = (float)d + 1.0f;
        float s1, c1, s2, c2;
        __sincosf(1.5f * atanf(__logf(kv + 1e-10f)), &s1, &c1);
        __sincosf(0.8f * __sinf(0.1f * kv), &s2, &c2);
        float fr = 0.7f * c1 + 0.3f * c2;
        float fi = 0.7f * s1 + 0.3f * s2;
        float w1 = 0.6f + 0.4f * __sinf(0.1f * (float)d);
        float w2 = 0.4f + 0.6f * __cosf(0.15f * (float)d);

        float th1 = TH1 * (float)d;
        float th2 = TH2 * (float)d;
        float s, co;
        __sincosf(th1 * (float)c0, &s, &co);
        float m1r = co, m1i = s;
        __sincosf(th1, &s, &co);
        float e1r = co, e1i = s;
        __sincosf(th2 * (float)c0, &s, &co);
        float m2r = co, m2i = s;
        __sincosf(th2, &s, &co);
        float e2r = co, e2i = s;

        #pragma unroll
        for (int k = 0; k < 4; k++) {
            float u1r = w1 * (m1r * fr - m1i * fi);
            float u1i = w1 * (m1r * fi + m1i * fr);
            float u2r = w2 * (m2r * fr - m2i * fi);
            float u2i = w2 * (m2r * fi + m2i * fr);
            g_U[(c0 + k) * D + d] = make_float4(u1r, u1i, u2r, u2i);
            float t1r = m1r * e1r - m1i * e1i;
            float t1i = m1r * e1i + m1i * e1r;
            m1r = t1r; m1i = t1i;
            float t2r = m2r * e2r - m2i * e2i;
            float t2i = m2r * e2i + m2i * e2r;
            m2r = t2r; m2i = t2i;
        }

        if (gid < D) {
            float ph = 2.0f * PI * (float)gid * (1.0f / (float)D);
            float sp, cp, s2p, c2p;
            __sincosf(ph, &sp, &cp);
            __sincosf(2.0f * ph, &s2p, &c2p);
            g_phtab[gid] = make_float4(cp, sp, c2p, s2p);
            g_cols[gid] = make_float4(__ldg(&bias[gid]), __ldg(&gamma[gid]),
                                      __ldg(&beta_ln[gid]), 0.f);
        }
        if (gid >= 512 && gid < 512 + VOCAB) {
            int cc = gid - 512;
            float cpm = (float)cc * 0.01f;
            float s0, c0_, sb, cb, sc, ccc;
            __sincosf(cpm, &s0, &c0_);
            __sincosf(cpm * 1.3f, &sb, &cb);
            __sincosf(cpm * 0.7f, &sc, &ccc);
            g_tokA[cc] = make_float4(c0_, s0, cb, sb);
            g_tokB[cc] = make_float2(ccc, sc);
        }
    } else {
        const int n = gid - 12288;
        int ci = __ldg(&char_idx[n]);
        float lam = (float)ci * (1.0f / (float)VOCAB);
        float t = (float)__ldg(&positions[n]) * 0.01f;
        float omega = 2.0f * PI * 1.5f;
        float kwav = 2.0f * PI / 1.7f;
        float ph1 = omega * t - kwav * lam + 0.8f * lam * lam;
        float ph2 = omega * t * 1.5f - kwav * lam * 0.7f + 0.8f * lam * lam * 1.3f;
        float a1 = sinf(omega * t + 1.5f * lam);
        float a2 = cosf(omega * t * 0.8f + 1.5f * lam * 1.2f);
        float s, cc;
        sincosf(ph1, &s, &cc);
        float wf1r = a1 * cc, wf1i = a1 * s;
        sincosf(ph2, &s, &cc);
        float wf2r = a2 * cc, wf2i = a2 * s;
        g_wf[n] = make_float4(wf1r, wf1i, wf2r, wf2i);
    }
}

// ---------------- K1: V gemm, 256 threads, thread = (char-half, column) ---------
// grid (48, 4). Block (cg, q): chars {2cg, 2cg+1}, columns [q*128, (q+1)*128).
// Register double-buffered W tile; Gram sums in q==0 blocks.
__global__ __launch_bounds__(256) void vgemm_kernel(const float* __restrict__ W) {
    const int c0 = blockIdx.x * 2;
    const int q = blockIdx.y;
    const int tid = threadIdx.x;
    const int ch = tid >> 7;        // which char of the pair
    const int col = tid & 127;      // column within the 128-column slice
    const int wid = tid >> 5;       // 0..7
    const int lane = tid & 31;

    __shared__ float4 su[2][D];       // 16 KB
    __shared__ float tile[128][33];   // ~17 KB
    __shared__ float smr[4][8];

    #pragma unroll
    for (int l = 0; l < 4; l++) {
        int idx = tid + l * 256;              // 0..1023
        su[idx >> 9][idx & 511] = __ldg(&g_U[(c0 + (idx >> 9)) * D + (idx & 511)]);
    }
    __syncthreads();

    if (q == 0) {
        // warps 0-3 reduce char0, warps 4-7 reduce char1
        float s11 = 0.f, s22 = 0.f, s12r = 0.f, s12i = 0.f;
        #pragma unroll
        for (int l = 0; l < 4; l++) {
            float4 u = su[ch][col + l * 128];
            s11 += u.x * u.x + u.y * u.y;
            s22 += u.z * u.z + u.w * u.w;
            s12r += u.x * u.z + u.y * u.w;
            s12i += u.y * u.z - u.x * u.w;
        }
        #pragma unroll
        for (int o = 16; o > 0; o >>= 1) {
            s11 += __shfl_xor_sync(0xffffffffu, s11, o);
            s22 += __shfl_xor_sync(0xffffffffu, s22, o);
            s12r += __shfl_xor_sync(0xffffffffu, s12r, o);
            s12i += __shfl_xor_sync(0xffffffffu, s12i, o);
        }
        if (lane == 0) {
            smr[0][wid] = s11; smr[1][wid] = s22;
            smr[2][wid] = s12r; smr[3][wid] = s12i;
        }
        __syncthreads();
        if ((tid & 127) == 0) {
            int b = ch * 4;
            g_S[c0 + ch] = make_float4(smr[0][b] + smr[0][b+1] + smr[0][b+2] + smr[0][b+3],
                                       smr[1][b] + smr[1][b+1] + smr[1][b+2] + smr[1][b+3],
                                       smr[2][b] + smr[2][b+1] + smr[2][b+2] + smr[2][b+3],
                                       smr[3][b] + smr[3][b+1] + smr[3][b+2] + smr[3][b+3]);
        }
    }

    // ---- GEMM: acc for V[c0+ch, q*128+col], double-buffered W tile ----
    const int dpbase = q * 128;
    float acc0 = 0.f, acc1 = 0.f, acc2 = 0.f, acc3 = 0.f;

    float4 r[4];
    #pragma unroll
    for (int l = 0; l < 4; l++) {          // prefetch chunk 0
        int f = tid + l * 256;
        int row = f >> 3, c4 = (f & 7) * 4;
        r[l] = *(const float4*)(W + (size_t)(dpbase + row) * D + c4);
    }

    #pragma unroll 1
    for (int chunk = 0; chunk < 16; chunk++) {
        __syncthreads();                   // previous FMA phase done
        #pragma unroll
        for (int l = 0; l < 4; l++) {
            int f = tid + l * 256;
            int row = f >> 3, c4 = (f & 7) * 4;
            tile[row][c4 + 0] = r[l].x;
            tile[row][c4 + 1] = r[l].y;
            tile[row][c4 + 2] = r[l].z;
            tile[row][c4 + 3] = r[l].w;
        }
        __syncthreads();
        if (chunk < 15) {                  // prefetch next chunk (hides L2 latency)
            #pragma unroll
            for (int l = 0; l < 4; l++) {
                int f = tid + l * 256;
                int row = f >> 3, c4 = (f & 7) * 4;
                r[l] = *(const float4*)(W + (size_t)(dpbase + row) * D
                                        + (chunk + 1) * 32 + c4);
            }
        }
        const int dk = chunk * 32;
        #pragma unroll
        for (int k = 0; k < 32; k++) {
            float wv = tile[col][k];
            float4 u = su[ch][dk + k];     // warp-broadcast
            acc0 = fmaf(u.x, wv, acc0);
            acc1 = fmaf(u.y, wv, acc1);
            acc2 = fmaf(u.z, wv, acc2);
            acc3 = fmaf(u.w, wv, acc3);
        }
    }
    g_V[(c0 + ch) * D + dpbase + col] = make_float4(acc0, acc1, acc2, acc3);
}

// ---------------- K2: fused coef + xw + LayerNorm + noise + quaternion ----------
// 128-thread group processes 4 tokens sequentially (tables amortized in regs);
// 2 groups per 256-thread block -> 8 tokens/block, grid = N_TOK/8. (R12 shape.)
__global__ __launch_bounds__(256, 4) void main_kernel(const int* __restrict__ char_idx,
                                                      const float* __restrict__ noise,
                                                      const float* __restrict__ sem,
                                                      float4* __restrict__ out) {
    __shared__ float red_s[8], red_ss[8];

    const int tid = threadIdx.x;
    const int grp = tid >> 7;
    const int gt = tid & 127;
    const int lane = tid & 31;
    const int wid = tid >> 5;
    const int nbase = blockIdx.x * 8 + grp * 4;

    float4 colr[4], phr[4];
    #pragma unroll
    for (int k = 0; k < 4; k++) {
        colr[k] = __ldg(&g_cols[k * 128 + gt]);
        phr[k]  = __ldg(&g_phtab[k * 128 + gt]);
    }

    const float ct = 0.995004165278025766f;
    const float st = 0.0998334166468281523f;

    #pragma unroll 1
    for (int t = 0; t < 4; t++) {
        const int n = nbase + t;
        const int c = __ldg(&char_idx[n]);
        const float4 wf = __ldg(&g_wf[n]);
        const float4 S = __ldg(&g_S[c]);

        float n1 = wf.x * wf.x + wf.y * wf.y;
        float n2 = wf.z * wf.z + wf.w * wf.w;
        float Ar = wf.x * wf.z + wf.y * wf.w;
        float Ai = wf.y * wf.z - wf.x * wf.w;
        float nrm2 = n1 * S.x + n2 * S.y + 2.0f * (Ar * S.z - Ai * S.w);
        float rinv = 1.0f / (sqrtf(nrm2) + 1e-8f);
        const float p1 = (wf.x * ct - wf.y * st) * rinv;
        const float q1 = -(wf.y * ct + wf.x * st) * rinv;
        const float p2 = (wf.z * ct - wf.w * st) * rinv;
        const float q2 = -(wf.w * ct + wf.z * st) * rinv;

        const float4* vrow = g_V + c * D;
        const float* nrow = noise + (size_t)n * D;
        float xw[4], nz[4];
        float s = 0.f, ss = 0.f;
        #pragma unroll
        for (int k = 0; k < 4; k++) {
            const int d = k * 128 + gt;
            float4 v = __ldg(&vrow[d]);
            nz[k] = __ldcs(&nrow[d]);
            float x = fmaf(p1, v.x, fmaf(q1, v.y, fmaf(p2, v.z, q2 * v.w))) + colr[k].x;
            xw[k] = x;
            s += x;
            ss = fmaf(x, x, ss);
        }
        #pragma unroll
        for (int o = 16; o > 0; o >>= 1) {
            s += __shfl_xor_sync(0xffffffffu, s, o);
            ss += __shfl_xor_sync(0xffffffffu, ss, o);
        }
        __syncthreads();
        if (lane == 0) { red_s[wid] = s; red_ss[wid] = ss; }
        __syncthreads();
        const int rb = grp * 4;
        float ts = red_s[rb] + red_s[rb + 1] + red_s[rb + 2] + red_s[rb + 3];
        float tss = red_ss[rb] + red_ss[rb + 1] + red_ss[rb + 2] + red_ss[rb + 3];
        const float mu = ts * (1.0f / (float)D);
        const float rstd = rsqrtf(tss * (1.0f / (float)D) - mu * mu + 1e-5f);

        const float sw0 = __ldg(&sem[c * 4 + 0]);
        const float sw1 = __ldg(&sem[c * 4 + 1]);
        const float sw2 = __ldg(&sem[c * 4 + 2]);
        const float4 tA = __ldg(&g_tokA[c]);
        const float2 tB = __ldg(&g_tokB[c]);

        float4* orow = out + (size_t)n * D;
        #pragma unroll
        for (int k = 0; k < 4; k++) {
            const int d = k * 128 + gt;
            float y = (xw[k] - mu) * rstd * colr[k].y + colr[k].z + 0.01f * nz[k];
            float4 ph = phr[k];
            float4 o;
            o.x = y;
            o.y = y * sw0 * (ph.x * tA.x - ph.y * tA.y);   // cos(phase + cpm)
            o.z = y * sw1 * (ph.y * tA.z + ph.x * tA.w);   // sin(phase + 1.3cpm)
            o.w = y * sw2 * (ph.z * tB.x - ph.w * tB.y);   // cos(2phase + 0.7cpm)
            __stcs(&orow[d], o);
        }
    }
}

// ---------------- launch ----------------
extern "C" void kernel_launch(void* const* d_in, const int* in_sizes, int n_in,
                              void* d_out, int out_size) {
    const int*   char_idx  = (const int*)d_in[0];
    const int*   positions = (const int*)d_in[1];
    const float* W         = (const float*)d_in[2];
    const float* b         = (const float*)d_in[3];
    const float* gamma     = (const float*)d_in[4];
    const float* beta_ln   = (const float*)d_in[5];
    const float* noise     = (const float*)d_in[6];
    const float* sem       = (const float*)d_in[7];
    float4* out = (float4*)d_out;

    setup_kernel<<<112, 256>>>(char_idx, positions, b, gamma, beta_ln);
    vgemm_kernel<<<dim3(VOCAB / 2, 4), 256>>>(W);
    main_kernel<<<N_TOK / 8, 256>>>(char_idx, noise, sem, out);
}

// round 14
// speedup vs baseline: 1.0304x; 1.0304x over previous
#include <cuda_runtime.h>
#include <math.h>
#include <stdint.h>

#define N_TOK 16384
#define D 512
#define VOCAB 96

// ---------------- device scratch ----------------
__device__ float4 g_V[VOCAB * D];    // (V1r, V1i, V2r, V2i) = U @ W^T
__device__ float4 g_S[VOCAB];        // (S11, S22, S12r, S12i)
__device__ float4 g_phtab[D];        // cosP, sinP, cos2P, sin2P
__device__ float4 g_cols[D];         // bias, gamma, beta, 0
__device__ float4 g_wf[N_TOK];       // wf1r, wf1i, wf2r, wf2i
__device__ float4 g_tokA[VOCAB];     // cos(cpm), sin(cpm), cos(1.3cpm), sin(1.3cpm)
__device__ float2 g_tokB[VOCAB];     // cos(.7cpm), sin(.7cpm)

// ---------------- K0: fused prep — in-block U (256 thr) + tables + DB GEMM ----
// grid (48, 4), 256 threads. Block (cg, q): chars {2cg, 2cg+1},
// V columns [q*128, (q+1)*128). thread = (ch = tid>>7, col = tid&127).
__global__ __launch_bounds__(256) void prep_kernel(const int* __restrict__ char_idx,
                                                   const int* __restrict__ positions,
                                                   const float* __restrict__ W,
                                                   const float* __restrict__ bias,
                                                   const float* __restrict__ gamma,
                                                   const float* __restrict__ beta_ln) {
    const int c0 = blockIdx.x * 2;
    const int q = blockIdx.y;
    const int tid = threadIdx.x;
    const int ch = tid >> 7;
    const int col = tid & 127;
    const int wid = tid >> 5;
    const int lane = tid & 31;
    const int gid = (blockIdx.y * 48 + blockIdx.x) * 256 + tid;  // 0..49151
    const float PI = 3.14159265358979323846f;
    const float TH1 = 2.0f * PI / ((float)VOCAB * (float)D);
    const float TH2 = 4.0f * PI * 1.7f / ((float)VOCAB * (float)D);

    __shared__ float4 su[2][D];       // 16 KB
    __shared__ float tile[128][33];   // ~17 KB
    __shared__ float smr[4][8];

    // ---- U rows for chars c0, c0+1: each thread handles d = tid, tid+256 ----
    #pragma unroll
    for (int l = 0; l < 2; l++) {
        const int d = tid + l * 256;
        float kv = (float)d + 1.0f;
        float s1, c1, s2, c2;
        __sincosf(1.5f * atanf(__logf(kv + 1e-10f)), &s1, &c1);
        __sincosf(0.8f * __sinf(0.1f * kv), &s2, &c2);
        float fr = 0.7f * c1 + 0.3f * c2;
        float fi = 0.7f * s1 + 0.3f * s2;
        float w1 = 0.6f + 0.4f * __sinf(0.1f * (float)d);
        float w2 = 0.4f + 0.6f * __cosf(0.15f * (float)d);
        float th1d = TH1 * (float)d;
        float th2d = TH2 * (float)d;
        #pragma unroll
        for (int cc = 0; cc < 2; cc++) {
            float s, co;
            __sincosf(th1d * (float)(c0 + cc), &s, &co);
            float u1r = w1 * (co * fr - s * fi);
            float u1i = w1 * (co * fi + s * fr);
            __sincosf(th2d * (float)(c0 + cc), &s, &co);
            float u2r = w2 * (co * fr - s * fi);
            float u2i = w2 * (co * fi + s * fr);
            su[cc][d] = make_float4(u1r, u1i, u2r, u2i);
        }
    }

    // ---- side jobs (independent of su) ----
    if (gid < N_TOK) {
        // precise trig: phases reach ~50 rad
        int ci = __ldg(&char_idx[gid]);
        float lam = (float)ci * (1.0f / (float)VOCAB);
        float t = (float)__ldg(&positions[gid]) * 0.01f;
        float omega = 2.0f * PI * 1.5f;
        float kwav = 2.0f * PI / 1.7f;
        float ph1 = omega * t - kwav * lam + 0.8f * lam * lam;
        float ph2 = omega * t * 1.5f - kwav * lam * 0.7f + 0.8f * lam * lam * 1.3f;
        float a1 = sinf(omega * t + 1.5f * lam);
        float a2 = cosf(omega * t * 0.8f + 1.5f * lam * 1.2f);
        float s, cc;
        sincosf(ph1, &s, &cc);
        float wf1r = a1 * cc, wf1i = a1 * s;
        sincosf(ph2, &s, &cc);
        float wf2r = a2 * cc, wf2i = a2 * s;
        g_wf[gid] = make_float4(wf1r, wf1i, wf2r, wf2i);
    }
    if (gid < D) {
        float ph = 2.0f * PI * (float)gid * (1.0f / (float)D);
        float sp, cp, s2p, c2p;
        __sincosf(ph, &sp, &cp);
        __sincosf(2.0f * ph, &s2p, &c2p);
        g_phtab[gid] = make_float4(cp, sp, c2p, s2p);
        g_cols[gid] = make_float4(__ldg(&bias[gid]), __ldg(&gamma[gid]),
                                  __ldg(&beta_ln[gid]), 0.f);
    }
    if (gid >= 16384 && gid < 16384 + VOCAB) {
        int cc = gid - 16384;
        float cpm = (float)cc * 0.01f;
        float s0, c0_, sb, cb, sc, ccc;
        __sincosf(cpm, &s0, &c0_);
        __sincosf(cpm * 1.3f, &sb, &cb);
        __sincosf(cpm * 0.7f, &sc, &ccc);
        g_tokA[cc] = make_float4(c0_, s0, cb, sb);
        g_tokB[cc] = make_float2(ccc, sc);
    }
    __syncthreads();

    // ---- Gram sums (q == 0 blocks): warps 0-3 char0, warps 4-7 char1 ----
    if (q == 0) {
        float s11 = 0.f, s22 = 0.f, s12r = 0.f, s12i = 0.f;
        #pragma unroll
        for (int l = 0; l < 4; l++) {
            float4 u = su[ch][col + l * 128];
            s11 += u.x * u.x + u.y * u.y;
            s22 += u.z * u.z + u.w * u.w;
            s12r += u.x * u.z + u.y * u.w;
            s12i += u.y * u.z - u.x * u.w;
        }
        #pragma unroll
        for (int o = 16; o > 0; o >>= 1) {
            s11 += __shfl_xor_sync(0xffffffffu, s11, o);
            s22 += __shfl_xor_sync(0xffffffffu, s22, o);
            s12r += __shfl_xor_sync(0xffffffffu, s12r, o);
            s12i += __shfl_xor_sync(0xffffffffu, s12i, o);
        }
        if (lane == 0) {
            smr[0][wid] = s11; smr[1][wid] = s22;
            smr[2][wid] = s12r; smr[3][wid] = s12i;
        }
        __syncthreads();
        if ((tid & 127) == 0) {
            int b = ch * 4;
            g_S[c0 + ch] = make_float4(smr[0][b] + smr[0][b+1] + smr[0][b+2] + smr[0][b+3],
                                       smr[1][b] + smr[1][b+1] + smr[1][b+2] + smr[1][b+3],
                                       smr[2][b] + smr[2][b+1] + smr[2][b+2] + smr[2][b+3],
                                       smr[3][b] + smr[3][b+1] + smr[3][b+2] + smr[3][b+3]);
        }
    }

    // ---- GEMM: acc for V[c0+ch, q*128+col], register double-buffered W tile ----
    const int dpbase = q * 128;
    float acc0 = 0.f, acc1 = 0.f, acc2 = 0.f, acc3 = 0.f;

    float4 r[4];
    #pragma unroll
    for (int l = 0; l < 4; l++) {          // prefetch chunk 0
        int f = tid + l * 256;
        int row = f >> 3, c4 = (f & 7) * 4;
        r[l] = *(const float4*)(W + (size_t)(dpbase + row) * D + c4);
    }

    #pragma unroll 1
    for (int chunk = 0; chunk < 16; chunk++) {
        __syncthreads();
        #pragma unroll
        for (int l = 0; l < 4; l++) {
            int f = tid + l * 256;
            int row = f >> 3, c4 = (f & 7) * 4;
            tile[row][c4 + 0] = r[l].x;
            tile[row][c4 + 1] = r[l].y;
            tile[row][c4 + 2] = r[l].z;
            tile[row][c4 + 3] = r[l].w;
        }
        __syncthreads();
        if (chunk < 15) {                  // prefetch next chunk, hides L2 latency
            #pragma unroll
            for (int l = 0; l < 4; l++) {
                int f = tid + l * 256;
                int row = f >> 3, c4 = (f & 7) * 4;
                r[l] = *(const float4*)(W + (size_t)(dpbase + row) * D
                                        + (chunk + 1) * 32 + c4);
            }
        }
        const int dk = chunk * 32;
        #pragma unroll
        for (int k = 0; k < 32; k++) {
            float wv = tile[col][k];
            float4 u = su[ch][dk + k];     // warp-broadcast
            acc0 = fmaf(u.x, wv, acc0);
            acc1 = fmaf(u.y, wv, acc1);
            acc2 = fmaf(u.z, wv, acc2);
            acc3 = fmaf(u.w, wv, acc3);
        }
    }
    g_V[(c0 + ch) * D + dpbase + col] = make_float4(acc0, acc1, acc2, acc3);
}

// ---------------- K1: fused coef + xw + LayerNorm + noise + quaternion ----------
// 128-thread group processes 4 tokens sequentially (tables amortized in regs);
// 2 groups per 256-thread block -> 8 tokens/block, grid = N_TOK/8. (R12 shape.)
__global__ __launch_bounds__(256, 4) void main_kernel(const int* __restrict__ char_idx,
                                                      const float* __restrict__ noise,
                                                      const float* __restrict__ sem,
                                                      float4* __restrict__ out) {
    __shared__ float red_s[8], red_ss[8];

    const int tid = threadIdx.x;
    const int grp = tid >> 7;
    const int gt = tid & 127;
    const int lane = tid & 31;
    const int wid = tid >> 5;
    const int nbase = blockIdx.x * 8 + grp * 4;

    float4 colr[4], phr[4];
    #pragma unroll
    for (int k = 0; k < 4; k++) {
        colr[k] = __ldg(&g_cols[k * 128 + gt]);
        phr[k]  = __ldg(&g_phtab[k * 128 + gt]);
    }

    const float ct = 0.995004165278025766f;
    const float st = 0.0998334166468281523f;

    #pragma unroll 1
    for (int t = 0; t < 4; t++) {
        const int n = nbase + t;
        const int c = __ldg(&char_idx[n]);
        const float4 wf = __ldg(&g_wf[n]);
        const float4 S = __ldg(&g_S[c]);

        float n1 = wf.x * wf.x + wf.y * wf.y;
        float n2 = wf.z * wf.z + wf.w * wf.w;
        float Ar = wf.x * wf.z + wf.y * wf.w;
        float Ai = wf.y * wf.z - wf.x * wf.w;
        float nrm2 = n1 * S.x + n2 * S.y + 2.0f * (Ar * S.z - Ai * S.w);
        float rinv = 1.0f / (sqrtf(nrm2) + 1e-8f);
        const float p1 = (wf.x * ct - wf.y * st) * rinv;
        const float q1 = -(wf.y * ct + wf.x * st) * rinv;
        const float p2 = (wf.z * ct - wf.w * st) * rinv;
        const float q2 = -(wf.w * ct + wf.z * st) * rinv;

        const float4* vrow = g_V + c * D;
        const float* nrow = noise + (size_t)n * D;
        float xw[4], nz[4];
        float s = 0.f, ss = 0.f;
        #pragma unroll
        for (int k = 0; k < 4; k++) {
            const int d = k * 128 + gt;
            float4 v = __ldg(&vrow[d]);
            nz[k] = __ldcs(&nrow[d]);
            float x = fmaf(p1, v.x, fmaf(q1, v.y, fmaf(p2, v.z, q2 * v.w))) + colr[k].x;
            xw[k] = x;
            s += x;
            ss = fmaf(x, x, ss);
        }
        #pragma unroll
        for (int o = 16; o > 0; o >>= 1) {
            s += __shfl_xor_sync(0xffffffffu, s, o);
            ss += __shfl_xor_sync(0xffffffffu, ss, o);
        }
        __syncthreads();
        if (lane == 0) { red_s[wid] = s; red_ss[wid] = ss; }
        __syncthreads();
        const int rb = grp * 4;
        float ts = red_s[rb] + red_s[rb + 1] + red_s[rb + 2] + red_s[rb + 3];
        float tss = red_ss[rb] + red_ss[rb + 1] + red_ss[rb + 2] + red_ss[rb + 3];
        const float mu = ts * (1.0f / (float)D);
        const float rstd = rsqrtf(tss * (1.0f / (float)D) - mu * mu + 1e-5f);

        const float sw0 = __ldg(&sem[c * 4 + 0]);
        const float sw1 = __ldg(&sem[c * 4 + 1]);
        const float sw2 = __ldg(&sem[c * 4 + 2]);
        const float4 tA = __ldg(&g_tokA[c]);
        const float2 tB = __ldg(&g_tokB[c]);

        float4* orow = out + (size_t)n * D;
        #pragma unroll
        for (int k = 0; k < 4; k++) {
            const int d = k * 128 + gt;
            float y = (xw[k] - mu) * rstd * colr[k].y + colr[k].z + 0.01f * nz[k];
            float4 ph = phr[k];
            float4 o;
            o.x = y;
            o.y = y * sw0 * (ph.x * tA.x - ph.y * tA.y);   // cos(phase + cpm)
            o.z = y * sw1 * (ph.y * tA.z + ph.x * tA.w);   // sin(phase + 1.3cpm)
            o.w = y * sw2 * (ph.z * tB.x - ph.w * tB.y);   // cos(2phase + 0.7cpm)
            __stcs(&orow[d], o);
        }
    }
}

// ---------------- launch ----------------
extern "C" void kernel_launch(void* const* d_in, const int* in_sizes, int n_in,
                              void* d_out, int out_size) {
    const int*   char_idx  = (const int*)d_in[0];
    const int*   positions = (const int*)d_in[1];
    const float* W         = (const float*)d_in[2];
    const float* b         = (const float*)d_in[3];
    const float* gamma     = (const float*)d_in[4];
    const float* beta_ln   = (const float*)d_in[5];
    const float* noise     = (const float*)d_in[6];
    const float* sem       = (const float*)d_in[7];
    float4* out = (float4*)d_out;

    prep_kernel<<<dim3(VOCAB / 2, 4), 256>>>(char_idx, positions, W, b, gamma, beta_ln);
    main_kernel<<<N_TOK / 8, 256>>>(char_idx, noise, sem, out);
}